// round 1
// baseline (speedup 1.0000x reference)
#include <cuda_runtime.h>

// Problem constants (shapes fixed by reference: B=16, NX=NY=1024)
#define NXc 1024
#define NYc 1024
#define NB  16
#define PLANE (NXc * NYc)

// product P(x,y) = grid(x,y) * f_b(x,y)
__device__ __forceinline__ float PF(const float* __restrict__ g,
                                    const float* __restrict__ fb,
                                    int x, int y) {
    int i = x * NYc + y;
    return __ldg(g + i) * __ldg(fb + i);
}

// d/dx of (g*f) with edge_order=2 one-sided closures
__device__ __forceinline__ float gx_p(const float* __restrict__ g,
                                      const float* __restrict__ fb,
                                      int x, int y) {
    if (x == 0)
        return 0.5f * (-3.0f * PF(g, fb, 0, y) + 4.0f * PF(g, fb, 1, y) - PF(g, fb, 2, y));
    if (x == NXc - 1)
        return 0.5f * ( 3.0f * PF(g, fb, x, y) - 4.0f * PF(g, fb, x - 1, y) + PF(g, fb, x - 2, y));
    return 0.5f * (PF(g, fb, x + 1, y) - PF(g, fb, x - 1, y));
}

// d/dy of (g*f)
__device__ __forceinline__ float gy_p(const float* __restrict__ g,
                                      const float* __restrict__ fb,
                                      int x, int y) {
    if (y == 0)
        return 0.5f * (-3.0f * PF(g, fb, x, 0) + 4.0f * PF(g, fb, x, 1) - PF(g, fb, x, 2));
    if (y == NYc - 1)
        return 0.5f * ( 3.0f * PF(g, fb, x, y) - 4.0f * PF(g, fb, x, y - 1) + PF(g, fb, x, y - 2));
    return 0.5f * (PF(g, fb, x, y + 1) - PF(g, fb, x, y - 1));
}

// d2/dx2 of (g*f) with one-sided 2nd-order boundary stencils
__device__ __forceinline__ float gxx_p(const float* __restrict__ g,
                                       const float* __restrict__ fb,
                                       int x, int y) {
    if (x == 0)
        return 2.0f * PF(g, fb, 0, y) - 5.0f * PF(g, fb, 1, y)
             + 4.0f * PF(g, fb, 2, y) - PF(g, fb, 3, y);
    if (x == NXc - 1)
        return 2.0f * PF(g, fb, x, y) - 5.0f * PF(g, fb, x - 1, y)
             + 4.0f * PF(g, fb, x - 2, y) - PF(g, fb, x - 3, y);
    return PF(g, fb, x + 1, y) - 2.0f * PF(g, fb, x, y) + PF(g, fb, x - 1, y);
}

// d2/dy2 of (g*f)
__device__ __forceinline__ float gyy_p(const float* __restrict__ g,
                                       const float* __restrict__ fb,
                                       int x, int y) {
    if (y == 0)
        return 2.0f * PF(g, fb, x, 0) - 5.0f * PF(g, fb, x, 1)
             + 4.0f * PF(g, fb, x, 2) - PF(g, fb, x, 3);
    if (y == NYc - 1)
        return 2.0f * PF(g, fb, x, y) - 5.0f * PF(g, fb, x, y - 1)
             + 4.0f * PF(g, fb, x, y - 2) - PF(g, fb, x, y - 3);
    return PF(g, fb, x, y + 1) - 2.0f * PF(g, fb, x, y) + PF(g, fb, x, y - 1);
}

// Gy = d/dy of (B2*f) at (x,y) — inner op of mixed derivative
__device__ __forceinline__ float Gy(const float* __restrict__ g,
                                    const float* __restrict__ fb,
                                    int x, int y) {
    return gy_p(g, fb, x, y);
}

// mixed derivative M = d/dx ( d/dy (B2*f) )
__device__ __forceinline__ float mixed_p(const float* __restrict__ g,
                                         const float* __restrict__ fb,
                                         int x, int y) {
    if (x == 0)
        return 0.5f * (-3.0f * Gy(g, fb, 0, y) + 4.0f * Gy(g, fb, 1, y) - Gy(g, fb, 2, y));
    if (x == NXc - 1)
        return 0.5f * ( 3.0f * Gy(g, fb, x, y) - 4.0f * Gy(g, fb, x - 1, y) + Gy(g, fb, x - 2, y));
    return 0.5f * (Gy(g, fb, x + 1, y) - Gy(g, fb, x - 1, y));
}

__global__ void __launch_bounds__(256)
fokker_planck_kernel(const float* __restrict__ f,
                     const float* __restrict__ A,
                     const float* __restrict__ Bg,
                     const float* __restrict__ dt,
                     float* __restrict__ out) {
    int y = blockIdx.x * blockDim.x + threadIdx.x;   // contiguous dim
    int x = blockIdx.y;
    int b = blockIdx.z;
    if (y >= NYc) return;

    const float* fb = f + (size_t)b * PLANE;
    const float* A0 = A;
    const float* A1 = A + PLANE;
    const float* B0 = Bg;
    const float* B1 = Bg + PLANE;
    const float* B2 = Bg + 2 * PLANE;

    float gradAf  = gx_p(A0, fb, x, y) + gy_p(A1, fb, x, y);

    // grad(grad(Bf2,2),1) + grad(grad(Bf2,1),2) == 2 * grad_x(grad_y(Bf2))
    // (tensor-product linear stencils commute exactly)
    float m       = mixed_p(B2, fb, x, y);
    float gradvv  = gxx_p(B0, fb, x, y) + gyy_p(B1, fb, x, y) + 2.0f * m;

    int i = x * NYc + y;
    float fc  = __ldg(fb + i);
    float df  = -gradAf + 0.5f * gradvv;
    float val = fmaf(df, __ldg(dt + b), fc);

    out[(size_t)b * PLANE + i] = fmaxf(val, 0.0f);
}

extern "C" void kernel_launch(void* const* d_in, const int* in_sizes, int n_in,
                              void* d_out, int out_size) {
    const float* f  = (const float*)d_in[0];   // [16,1024,1024]
    const float* A  = (const float*)d_in[1];   // [2,1024,1024]
    const float* Bg = (const float*)d_in[2];   // [3,1024,1024]
    const float* dt = (const float*)d_in[3];   // [16]
    float* out = (float*)d_out;

    dim3 block(256, 1, 1);
    dim3 grid(NYc / 256, NXc, NB);
    fokker_planck_kernel<<<grid, block>>>(f, A, Bg, dt, out);
}

// round 3
// speedup vs baseline: 1.2273x; 1.2273x over previous
#include <cuda_runtime.h>

#define NXc 1024
#define NYc 1024
#define NB  16
#define PLANE (NXc * NYc)
#define ROWS_PER_BLOCK 16
#define XCHUNKS (NXc / ROWS_PER_BLOCK)

// ======================= slow path (x-boundary rows) =======================

__device__ __forceinline__ float PF(const float* __restrict__ g,
                                    const float* __restrict__ fb,
                                    int x, int y) {
    int i = x * NYc + y;
    return __ldg(g + i) * __ldg(fb + i);
}

__device__ __forceinline__ float gx_p(const float* __restrict__ g,
                                      const float* __restrict__ fb,
                                      int x, int y) {
    if (x == 0)
        return 0.5f * (-3.0f * PF(g, fb, 0, y) + 4.0f * PF(g, fb, 1, y) - PF(g, fb, 2, y));
    if (x == NXc - 1)
        return 0.5f * ( 3.0f * PF(g, fb, x, y) - 4.0f * PF(g, fb, x - 1, y) + PF(g, fb, x - 2, y));
    return 0.5f * (PF(g, fb, x + 1, y) - PF(g, fb, x - 1, y));
}

__device__ __forceinline__ float gy_p(const float* __restrict__ g,
                                      const float* __restrict__ fb,
                                      int x, int y) {
    if (y == 0)
        return 0.5f * (-3.0f * PF(g, fb, x, 0) + 4.0f * PF(g, fb, x, 1) - PF(g, fb, x, 2));
    if (y == NYc - 1)
        return 0.5f * ( 3.0f * PF(g, fb, x, y) - 4.0f * PF(g, fb, x, y - 1) + PF(g, fb, x, y - 2));
    return 0.5f * (PF(g, fb, x, y + 1) - PF(g, fb, x, y - 1));
}

__device__ __forceinline__ float gxx_p(const float* __restrict__ g,
                                       const float* __restrict__ fb,
                                       int x, int y) {
    if (x == 0)
        return 2.0f * PF(g, fb, 0, y) - 5.0f * PF(g, fb, 1, y)
             + 4.0f * PF(g, fb, 2, y) - PF(g, fb, 3, y);
    if (x == NXc - 1)
        return 2.0f * PF(g, fb, x, y) - 5.0f * PF(g, fb, x - 1, y)
             + 4.0f * PF(g, fb, x - 2, y) - PF(g, fb, x - 3, y);
    return PF(g, fb, x + 1, y) - 2.0f * PF(g, fb, x, y) + PF(g, fb, x - 1, y);
}

__device__ __forceinline__ float gyy_p(const float* __restrict__ g,
                                       const float* __restrict__ fb,
                                       int x, int y) {
    if (y == 0)
        return 2.0f * PF(g, fb, x, 0) - 5.0f * PF(g, fb, x, 1)
             + 4.0f * PF(g, fb, x, 2) - PF(g, fb, x, 3);
    if (y == NYc - 1)
        return 2.0f * PF(g, fb, x, y) - 5.0f * PF(g, fb, x, y - 1)
             + 4.0f * PF(g, fb, x, y - 2) - PF(g, fb, x, y - 3);
    return PF(g, fb, x, y + 1) - 2.0f * PF(g, fb, x, y) + PF(g, fb, x, y - 1);
}

__device__ __forceinline__ float mixed_p(const float* __restrict__ g,
                                         const float* __restrict__ fb,
                                         int x, int y) {
    if (x == 0)
        return 0.5f * (-3.0f * gy_p(g, fb, 0, y) + 4.0f * gy_p(g, fb, 1, y) - gy_p(g, fb, 2, y));
    if (x == NXc - 1)
        return 0.5f * ( 3.0f * gy_p(g, fb, x, y) - 4.0f * gy_p(g, fb, x - 1, y) + gy_p(g, fb, x - 2, y));
    return 0.5f * (gy_p(g, fb, x + 1, y) - gy_p(g, fb, x - 1, y));
}

__device__ __forceinline__ void slow_row(
    int x, int y0,
    const float* __restrict__ fb,
    const float* __restrict__ A0, const float* __restrict__ A1,
    const float* __restrict__ B0, const float* __restrict__ B1,
    const float* __restrict__ B2,
    float dtb, float* __restrict__ ob)
{
    float r[4];
#pragma unroll
    for (int j = 0; j < 4; j++) {
        int y = y0 + j;
        float gradAf = gx_p(A0, fb, x, y) + gy_p(A1, fb, x, y);
        float m      = mixed_p(B2, fb, x, y);
        float gvv    = gxx_p(B0, fb, x, y) + gyy_p(B1, fb, x, y) + 2.0f * m;
        float fc     = __ldg(fb + x * NYc + y);
        r[j] = fmaxf(fmaf(-gradAf + 0.5f * gvv, dtb, fc), 0.0f);
    }
    *(float4*)(ob + x * NYc + y0) = make_float4(r[0], r[1], r[2], r[3]);
}

// ======================= fast path: per-row precompute =======================
// For row r, thread owning y0..y0+3 computes (indices 0..5 <-> y0-1..y0+4):
//   a0[4]  = A0*f at center lanes       (for gx, needs rows x±1)
//   b0[4]  = B0*f                        (for gxx, rows x-1,x,x+1)
//   g2[4]  = d/dy (B2*f)                 (for mixed, rows x±1)
//   hA1[4] = d/dy (A1*f)                 (row-local)
//   hB1[4] = d2/dy2 (B1*f)               (row-local)
//   fc[4]  = f                           (row-local)

__device__ __forceinline__ void load_row(
    int r, int y0, bool le, bool re,
    const float* __restrict__ fb,
    const float* __restrict__ A0, const float* __restrict__ A1,
    const float* __restrict__ B0, const float* __restrict__ B1,
    const float* __restrict__ B2,
    float* __restrict__ a0, float* __restrict__ b0, float* __restrict__ g2,
    float* __restrict__ hA1, float* __restrict__ hB1, float* __restrict__ fc)
{
    const int base = r * NYc + y0;

    float fv[6];
    {
        float4 t = *(const float4*)(fb + base);
        fv[1] = t.x; fv[2] = t.y; fv[3] = t.z; fv[4] = t.w;
        fv[0] = le ? 0.0f : __ldg(fb + base - 1);
        fv[5] = re ? 0.0f : __ldg(fb + base + 4);
    }

    {
        float4 a = *(const float4*)(A0 + base);
        a0[0] = a.x * fv[1]; a0[1] = a.y * fv[2];
        a0[2] = a.z * fv[3]; a0[3] = a.w * fv[4];
    }
    {
        float4 bb = *(const float4*)(B0 + base);
        b0[0] = bb.x * fv[1]; b0[1] = bb.y * fv[2];
        b0[2] = bb.z * fv[3]; b0[3] = bb.w * fv[4];
    }
    fc[0] = fv[1]; fc[1] = fv[2]; fc[2] = fv[3]; fc[3] = fv[4];

    float p[6];

    // ---- A1: first derivative along y ----
    {
        float4 a = *(const float4*)(A1 + base);
        p[1] = a.x * fv[1]; p[2] = a.y * fv[2]; p[3] = a.z * fv[3]; p[4] = a.w * fv[4];
        p[0] = le ? 0.0f : __ldg(A1 + base - 1) * fv[0];
        p[5] = re ? 0.0f : __ldg(A1 + base + 4) * fv[5];
#pragma unroll
        for (int j = 0; j < 4; j++) hA1[j] = 0.5f * (p[j + 2] - p[j]);
        if (le) hA1[0] = 0.5f * (-3.0f * p[1] + 4.0f * p[2] - p[3]);
        if (re) hA1[3] = 0.5f * ( 3.0f * p[4] - 4.0f * p[3] + p[2]);
    }

    // ---- B1: second derivative along y ----
    {
        float4 a = *(const float4*)(B1 + base);
        p[1] = a.x * fv[1]; p[2] = a.y * fv[2]; p[3] = a.z * fv[3]; p[4] = a.w * fv[4];
        p[0] = le ? 0.0f : __ldg(B1 + base - 1) * fv[0];
        p[5] = re ? 0.0f : __ldg(B1 + base + 4) * fv[5];
#pragma unroll
        for (int j = 0; j < 4; j++) hB1[j] = p[j + 2] - 2.0f * p[j + 1] + p[j];
        if (le) hB1[0] = 2.0f * p[1] - 5.0f * p[2] + 4.0f * p[3] - p[4];
        if (re) hB1[3] = 2.0f * p[4] - 5.0f * p[3] + 4.0f * p[2] - p[1];
    }

    // ---- B2: first derivative along y (inner op of mixed derivative) ----
    {
        float4 a = *(const float4*)(B2 + base);
        p[1] = a.x * fv[1]; p[2] = a.y * fv[2]; p[3] = a.z * fv[3]; p[4] = a.w * fv[4];
        p[0] = le ? 0.0f : __ldg(B2 + base - 1) * fv[0];
        p[5] = re ? 0.0f : __ldg(B2 + base + 4) * fv[5];
#pragma unroll
        for (int j = 0; j < 4; j++) g2[j] = 0.5f * (p[j + 2] - p[j]);
        if (le) g2[0] = 0.5f * (-3.0f * p[1] + 4.0f * p[2] - p[3]);
        if (re) g2[3] = 0.5f * ( 3.0f * p[4] - 4.0f * p[3] + p[2]);
    }
}

__global__ void __launch_bounds__(256, 2)
fp_fast(const float* __restrict__ f, const float* __restrict__ A,
        const float* __restrict__ Bg, const float* __restrict__ dt,
        float* __restrict__ out)
{
    const int y0    = threadIdx.x * 4;
    const int chunk = blockIdx.x;
    const int b     = blockIdx.y;
    const bool le = (y0 == 0);
    const bool re = (y0 == NYc - 4);

    const float* fb = f + (size_t)b * PLANE;
    const float* A0 = A;
    const float* A1 = A + PLANE;
    const float* B0 = Bg;
    const float* B1 = Bg + PLANE;
    const float* B2 = Bg + 2 * PLANE;
    const float dtb = __ldg(dt + b);
    float* ob = out + (size_t)b * PLANE;

    const int xs = chunk * ROWS_PER_BLOCK;
    const int xe = xs + ROWS_PER_BLOCK;

    float a0m[4], a0c[4], a0p[4];
    float b0m[4], b0c[4], b0p[4];
    float g2m[4], g2c[4], g2p[4];
    float hA1c[4], hA1p[4];
    float hB1c[4], hB1p[4];
    float fcc[4],  fcp[4];

    int x0;
    if (xs == 0) {
        slow_row(0, y0, fb, A0, A1, B0, B1, B2, dtb, ob);
        load_row(0, y0, le, re, fb, A0, A1, B0, B1, B2, a0m, b0m, g2m, hA1p, hB1p, fcp);
        load_row(1, y0, le, re, fb, A0, A1, B0, B1, B2, a0c, b0c, g2c, hA1c, hB1c, fcc);
        x0 = 1;
    } else {
        load_row(xs - 1, y0, le, re, fb, A0, A1, B0, B1, B2, a0m, b0m, g2m, hA1p, hB1p, fcp);
        load_row(xs,     y0, le, re, fb, A0, A1, B0, B1, B2, a0c, b0c, g2c, hA1c, hB1c, fcc);
        x0 = xs;
    }
    const int xlast = (xe == NXc) ? NXc - 1 : xe;

    for (int x = x0; x < xlast; x++) {
        load_row(x + 1, y0, le, re, fb, A0, A1, B0, B1, B2,
                 a0p, b0p, g2p, hA1p, hB1p, fcp);

        float r[4];
#pragma unroll
        for (int j = 0; j < 4; j++) {
            float gA = 0.5f * (a0p[j] - a0m[j]) + hA1c[j];                 // div of A*f
            float gB = (b0p[j] - 2.0f * b0c[j] + b0m[j])                   // gxx(B0 f)
                     + hB1c[j]                                             // gyy(B1 f)
                     + (g2p[j] - g2m[j]);                                  // 2*mixed
            float df = -gA + 0.5f * gB;
            r[j] = fmaxf(fmaf(df, dtb, fcc[j]), 0.0f);
        }
        *(float4*)(ob + x * NYc + y0) = make_float4(r[0], r[1], r[2], r[3]);

#pragma unroll
        for (int j = 0; j < 4; j++) {
            a0m[j] = a0c[j]; a0c[j] = a0p[j];
            b0m[j] = b0c[j]; b0c[j] = b0p[j];
            g2m[j] = g2c[j]; g2c[j] = g2p[j];
            hA1c[j] = hA1p[j];
            hB1c[j] = hB1p[j];
            fcc[j]  = fcp[j];
        }
    }

    if (xe == NXc) {
        slow_row(NXc - 1, y0, fb, A0, A1, B0, B1, B2, dtb, ob);
    }
}

extern "C" void kernel_launch(void* const* d_in, const int* in_sizes, int n_in,
                              void* d_out, int out_size) {
    const float* f  = (const float*)d_in[0];   // [16,1024,1024]
    const float* A  = (const float*)d_in[1];   // [2,1024,1024]
    const float* Bg = (const float*)d_in[2];   // [3,1024,1024]
    const float* dt = (const float*)d_in[3];   // [16]
    float* out = (float*)d_out;

    dim3 block(256, 1, 1);
    dim3 grid(XCHUNKS, NB, 1);
    fp_fast<<<grid, block>>>(f, A, Bg, dt, out);
}

// round 8
// speedup vs baseline: 1.4671x; 1.1954x over previous
#include <cuda_runtime.h>

#define NXc 1024
#define NYc 1024
#define NB  16
#define PLANE (NXc * NYc)
#define ROWS_PER_BLOCK 16
#define XCHUNKS (NXc / ROWS_PER_BLOCK)

// ======================= slow path (x-boundary rows) =======================

__device__ __forceinline__ float PF(const float* __restrict__ g,
                                    const float* __restrict__ fb,
                                    int x, int y) {
    int i = x * NYc + y;
    return __ldg(g + i) * __ldg(fb + i);
}

__device__ __forceinline__ float gx_p(const float* __restrict__ g,
                                      const float* __restrict__ fb,
                                      int x, int y) {
    if (x == 0)
        return 0.5f * (-3.0f * PF(g, fb, 0, y) + 4.0f * PF(g, fb, 1, y) - PF(g, fb, 2, y));
    if (x == NXc - 1)
        return 0.5f * ( 3.0f * PF(g, fb, x, y) - 4.0f * PF(g, fb, x - 1, y) + PF(g, fb, x - 2, y));
    return 0.5f * (PF(g, fb, x + 1, y) - PF(g, fb, x - 1, y));
}

__device__ __forceinline__ float gy_p(const float* __restrict__ g,
                                      const float* __restrict__ fb,
                                      int x, int y) {
    if (y == 0)
        return 0.5f * (-3.0f * PF(g, fb, x, 0) + 4.0f * PF(g, fb, x, 1) - PF(g, fb, x, 2));
    if (y == NYc - 1)
        return 0.5f * ( 3.0f * PF(g, fb, x, y) - 4.0f * PF(g, fb, x, y - 1) + PF(g, fb, x, y - 2));
    return 0.5f * (PF(g, fb, x, y + 1) - PF(g, fb, x, y - 1));
}

__device__ __forceinline__ float gxx_p(const float* __restrict__ g,
                                       const float* __restrict__ fb,
                                       int x, int y) {
    if (x == 0)
        return 2.0f * PF(g, fb, 0, y) - 5.0f * PF(g, fb, 1, y)
             + 4.0f * PF(g, fb, 2, y) - PF(g, fb, 3, y);
    if (x == NXc - 1)
        return 2.0f * PF(g, fb, x, y) - 5.0f * PF(g, fb, x - 1, y)
             + 4.0f * PF(g, fb, x - 2, y) - PF(g, fb, x - 3, y);
    return PF(g, fb, x + 1, y) - 2.0f * PF(g, fb, x, y) + PF(g, fb, x - 1, y);
}

__device__ __forceinline__ float gyy_p(const float* __restrict__ g,
                                       const float* __restrict__ fb,
                                       int x, int y) {
    if (y == 0)
        return 2.0f * PF(g, fb, x, 0) - 5.0f * PF(g, fb, x, 1)
             + 4.0f * PF(g, fb, x, 2) - PF(g, fb, x, 3);
    if (y == NYc - 1)
        return 2.0f * PF(g, fb, x, y) - 5.0f * PF(g, fb, x, y - 1)
             + 4.0f * PF(g, fb, x, y - 2) - PF(g, fb, x, y - 3);
    return PF(g, fb, x, y + 1) - 2.0f * PF(g, fb, x, y) + PF(g, fb, x, y - 1);
}

__device__ __forceinline__ float mixed_p(const float* __restrict__ g,
                                         const float* __restrict__ fb,
                                         int x, int y) {
    if (x == 0)
        return 0.5f * (-3.0f * gy_p(g, fb, 0, y) + 4.0f * gy_p(g, fb, 1, y) - gy_p(g, fb, 2, y));
    if (x == NXc - 1)
        return 0.5f * ( 3.0f * gy_p(g, fb, x, y) - 4.0f * gy_p(g, fb, x - 1, y) + gy_p(g, fb, x - 2, y));
    return 0.5f * (gy_p(g, fb, x + 1, y) - gy_p(g, fb, x - 1, y));
}

__device__ __forceinline__ void slow_row(
    int x, int y0,
    const float* __restrict__ fb,
    const float* __restrict__ A0, const float* __restrict__ A1,
    const float* __restrict__ B0, const float* __restrict__ B1,
    const float* __restrict__ B2,
    float dtb, float* __restrict__ ob)
{
    float r[4];
#pragma unroll
    for (int j = 0; j < 4; j++) {
        int y = y0 + j;
        float gradAf = gx_p(A0, fb, x, y) + gy_p(A1, fb, x, y);
        float m      = mixed_p(B2, fb, x, y);
        float gvv    = gxx_p(B0, fb, x, y) + gyy_p(B1, fb, x, y) + 2.0f * m;
        float fc     = __ldg(fb + x * NYc + y);
        r[j] = fmaxf(fmaf(-gradAf + 0.5f * gvv, dtb, fc), 0.0f);
    }
    *(float4*)(ob + x * NYc + y0) = make_float4(r[0], r[1], r[2], r[3]);
}

// ======================= fast path =======================
// Per-row precompute collapses the whole update to:
//   df(x) = P(x+1) + M(x-1) + C(x)
// with  P = 0.5*(b0 + g2 - a0)
//       M = 0.5*(b0 - g2 + a0)
//       C = 0.5*hB1 - b0 - hA1
// where a0=A0*f, b0=B0*f, g2=d/dy(B2*f), hA1=d/dy(A1*f), hB1=d2/dy2(B1*f).

__device__ __forceinline__ void load_row2(
    int r, int y0, bool le, bool re,
    const float* __restrict__ fb,
    const float* __restrict__ A0, const float* __restrict__ A1,
    const float* __restrict__ B0, const float* __restrict__ B1,
    const float* __restrict__ B2,
    float* __restrict__ P, float* __restrict__ M,
    float* __restrict__ C, float* __restrict__ fc)
{
    const int base = r * NYc + y0;

    float fv[6];
    {
        float4 t = *(const float4*)(fb + base);
        fv[1] = t.x; fv[2] = t.y; fv[3] = t.z; fv[4] = t.w;
        fv[0] = le ? 0.0f : __ldg(fb + base - 1);
        fv[5] = re ? 0.0f : __ldg(fb + base + 4);
    }
    fc[0] = fv[1]; fc[1] = fv[2]; fc[2] = fv[3]; fc[3] = fv[4];

    float a0[4], b0[4];
    {
        float4 a = *(const float4*)(A0 + base);
        a0[0] = a.x * fv[1]; a0[1] = a.y * fv[2];
        a0[2] = a.z * fv[3]; a0[3] = a.w * fv[4];
    }
    {
        float4 bb = *(const float4*)(B0 + base);
        b0[0] = bb.x * fv[1]; b0[1] = bb.y * fv[2];
        b0[2] = bb.z * fv[3]; b0[3] = bb.w * fv[4];
    }

    float p[6], hA1[4], hB1[4], g2[4];

    // ---- A1: first derivative along y ----
    {
        float4 a = *(const float4*)(A1 + base);
        p[1] = a.x * fv[1]; p[2] = a.y * fv[2]; p[3] = a.z * fv[3]; p[4] = a.w * fv[4];
        p[0] = le ? 0.0f : __ldg(A1 + base - 1) * fv[0];
        p[5] = re ? 0.0f : __ldg(A1 + base + 4) * fv[5];
#pragma unroll
        for (int j = 0; j < 4; j++) hA1[j] = 0.5f * (p[j + 2] - p[j]);
        if (le) hA1[0] = 0.5f * (-3.0f * p[1] + 4.0f * p[2] - p[3]);
        if (re) hA1[3] = 0.5f * ( 3.0f * p[4] - 4.0f * p[3] + p[2]);
    }

    // ---- B1: second derivative along y ----
    {
        float4 a = *(const float4*)(B1 + base);
        p[1] = a.x * fv[1]; p[2] = a.y * fv[2]; p[3] = a.z * fv[3]; p[4] = a.w * fv[4];
        p[0] = le ? 0.0f : __ldg(B1 + base - 1) * fv[0];
        p[5] = re ? 0.0f : __ldg(B1 + base + 4) * fv[5];
#pragma unroll
        for (int j = 0; j < 4; j++) hB1[j] = p[j + 2] - 2.0f * p[j + 1] + p[j];
        if (le) hB1[0] = 2.0f * p[1] - 5.0f * p[2] + 4.0f * p[3] - p[4];
        if (re) hB1[3] = 2.0f * p[4] - 5.0f * p[3] + 4.0f * p[2] - p[1];
    }

    // ---- B2: first derivative along y ----
    {
        float4 a = *(const float4*)(B2 + base);
        p[1] = a.x * fv[1]; p[2] = a.y * fv[2]; p[3] = a.z * fv[3]; p[4] = a.w * fv[4];
        p[0] = le ? 0.0f : __ldg(B2 + base - 1) * fv[0];
        p[5] = re ? 0.0f : __ldg(B2 + base + 4) * fv[5];
#pragma unroll
        for (int j = 0; j < 4; j++) g2[j] = 0.5f * (p[j + 2] - p[j]);
        if (le) g2[0] = 0.5f * (-3.0f * p[1] + 4.0f * p[2] - p[3]);
        if (re) g2[3] = 0.5f * ( 3.0f * p[4] - 4.0f * p[3] + p[2]);
    }

#pragma unroll
    for (int j = 0; j < 4; j++) {
        P[j] = 0.5f * (b0[j] + g2[j] - a0[j]);
        M[j] = 0.5f * (b0[j] - g2[j] + a0[j]);
        C[j] = 0.5f * hB1[j] - b0[j] - hA1[j];
    }
}

__global__ void __launch_bounds__(256, 3)
fp_fast(const float* __restrict__ f, const float* __restrict__ A,
        const float* __restrict__ Bg, const float* __restrict__ dt,
        float* __restrict__ out)
{
    const int y0    = threadIdx.x * 4;
    const int chunk = blockIdx.x;
    const int b     = blockIdx.y;
    const bool le = (y0 == 0);
    const bool re = (y0 == NYc - 4);

    const float* fb = f + (size_t)b * PLANE;
    const float* A0 = A;
    const float* A1 = A + PLANE;
    const float* B0 = Bg;
    const float* B1 = Bg + PLANE;
    const float* B2 = Bg + 2 * PLANE;
    const float dtb = __ldg(dt + b);
    float* ob = out + (size_t)b * PLANE;

    const int xs = chunk * ROWS_PER_BLOCK;
    const int xe = xs + ROWS_PER_BLOCK;

    // carried state: M(x-1), M(x), C(x), f(x)
    float Mm[4], Mc[4], Cc[4], fcc[4];
    float Pt[4], Mt[4], Ct[4], ft[4];

    int x0;
    if (xs == 0) {
        slow_row(0, y0, fb, A0, A1, B0, B1, B2, dtb, ob);
        load_row2(0, y0, le, re, fb, A0, A1, B0, B1, B2, Pt, Mm, Ct, ft);
        load_row2(1, y0, le, re, fb, A0, A1, B0, B1, B2, Pt, Mc, Cc, fcc);
        x0 = 1;
    } else {
        load_row2(xs - 1, y0, le, re, fb, A0, A1, B0, B1, B2, Pt, Mm, Ct, ft);
        load_row2(xs,     y0, le, re, fb, A0, A1, B0, B1, B2, Pt, Mc, Cc, fcc);
        x0 = xs;
    }
    const int xlast = (xe == NXc) ? NXc - 1 : xe;

#pragma unroll 2
    for (int x = x0; x < xlast; x++) {
        load_row2(x + 1, y0, le, re, fb, A0, A1, B0, B1, B2, Pt, Mt, Ct, ft);

        float r[4];
#pragma unroll
        for (int j = 0; j < 4; j++) {
            float df = Pt[j] + Mm[j] + Cc[j];
            r[j] = fmaxf(fmaf(df, dtb, fcc[j]), 0.0f);
        }
        *(float4*)(ob + x * NYc + y0) = make_float4(r[0], r[1], r[2], r[3]);

#pragma unroll
        for (int j = 0; j < 4; j++) {
            Mm[j] = Mc[j]; Mc[j] = Mt[j];
            Cc[j] = Ct[j]; fcc[j] = ft[j];
        }
    }

    if (xe == NXc) {
        slow_row(NXc - 1, y0, fb, A0, A1, B0, B1, B2, dtb, ob);
    }
}

extern "C" void kernel_launch(void* const* d_in, const int* in_sizes, int n_in,
                              void* d_out, int out_size) {
    const float* f  = (const float*)d_in[0];   // [16,1024,1024]
    const float* A  = (const float*)d_in[1];   // [2,1024,1024]
    const float* Bg = (const float*)d_in[2];   // [3,1024,1024]
    const float* dt = (const float*)d_in[3];   // [16]
    float* out = (float*)d_out;

    dim3 block(256, 1, 1);
    dim3 grid(XCHUNKS, NB, 1);
    fp_fast<<<grid, block>>>(f, A, Bg, dt, out);
}

// round 11
// speedup vs baseline: 2.0830x; 1.4198x over previous
#include <cuda_runtime.h>

#define NXc 1024
#define NYc 1024
#define NB  16
#define PLANE (NXc * NYc)
#define ROWS_PER_BLOCK 16
#define XCHUNKS (NXc / ROWS_PER_BLOCK)

// ======================= slow path (x-boundary rows) =======================

__device__ __forceinline__ float PF(const float* __restrict__ g,
                                    const float* __restrict__ fb,
                                    int x, int y) {
    int i = x * NYc + y;
    return __ldg(g + i) * __ldg(fb + i);
}

__device__ __forceinline__ float gx_p(const float* __restrict__ g,
                                      const float* __restrict__ fb,
                                      int x, int y) {
    if (x == 0)
        return 0.5f * (-3.0f * PF(g, fb, 0, y) + 4.0f * PF(g, fb, 1, y) - PF(g, fb, 2, y));
    if (x == NXc - 1)
        return 0.5f * ( 3.0f * PF(g, fb, x, y) - 4.0f * PF(g, fb, x - 1, y) + PF(g, fb, x - 2, y));
    return 0.5f * (PF(g, fb, x + 1, y) - PF(g, fb, x - 1, y));
}

__device__ __forceinline__ float gy_p(const float* __restrict__ g,
                                      const float* __restrict__ fb,
                                      int x, int y) {
    if (y == 0)
        return 0.5f * (-3.0f * PF(g, fb, x, 0) + 4.0f * PF(g, fb, x, 1) - PF(g, fb, x, 2));
    if (y == NYc - 1)
        return 0.5f * ( 3.0f * PF(g, fb, x, y) - 4.0f * PF(g, fb, x, y - 1) + PF(g, fb, x, y - 2));
    return 0.5f * (PF(g, fb, x, y + 1) - PF(g, fb, x, y - 1));
}

__device__ __forceinline__ float gxx_p(const float* __restrict__ g,
                                       const float* __restrict__ fb,
                                       int x, int y) {
    if (x == 0)
        return 2.0f * PF(g, fb, 0, y) - 5.0f * PF(g, fb, 1, y)
             + 4.0f * PF(g, fb, 2, y) - PF(g, fb, 3, y);
    if (x == NXc - 1)
        return 2.0f * PF(g, fb, x, y) - 5.0f * PF(g, fb, x - 1, y)
             + 4.0f * PF(g, fb, x - 2, y) - PF(g, fb, x - 3, y);
    return PF(g, fb, x + 1, y) - 2.0f * PF(g, fb, x, y) + PF(g, fb, x - 1, y);
}

__device__ __forceinline__ float gyy_p(const float* __restrict__ g,
                                       const float* __restrict__ fb,
                                       int x, int y) {
    if (y == 0)
        return 2.0f * PF(g, fb, x, 0) - 5.0f * PF(g, fb, x, 1)
             + 4.0f * PF(g, fb, x, 2) - PF(g, fb, x, 3);
    if (y == NYc - 1)
        return 2.0f * PF(g, fb, x, y) - 5.0f * PF(g, fb, x, y - 1)
             + 4.0f * PF(g, fb, x, y - 2) - PF(g, fb, x, y - 3);
    return PF(g, fb, x, y + 1) - 2.0f * PF(g, fb, x, y) + PF(g, fb, x, y - 1);
}

__device__ __forceinline__ float mixed_p(const float* __restrict__ g,
                                         const float* __restrict__ fb,
                                         int x, int y) {
    if (x == 0)
        return 0.5f * (-3.0f * gy_p(g, fb, 0, y) + 4.0f * gy_p(g, fb, 1, y) - gy_p(g, fb, 2, y));
    if (x == NXc - 1)
        return 0.5f * ( 3.0f * gy_p(g, fb, x, y) - 4.0f * gy_p(g, fb, x - 1, y) + gy_p(g, fb, x - 2, y));
    return 0.5f * (gy_p(g, fb, x + 1, y) - gy_p(g, fb, x - 1, y));
}

__device__ __forceinline__ void slow_row(
    int x, int y0,
    const float* __restrict__ fb,
    const float* __restrict__ A0, const float* __restrict__ A1,
    const float* __restrict__ B0, const float* __restrict__ B1,
    const float* __restrict__ B2,
    float dtb, float* __restrict__ ob)
{
    float r[4];
#pragma unroll
    for (int j = 0; j < 4; j++) {
        int y = y0 + j;
        float gradAf = gx_p(A0, fb, x, y) + gy_p(A1, fb, x, y);
        float m      = mixed_p(B2, fb, x, y);
        float gvv    = gxx_p(B0, fb, x, y) + gyy_p(B1, fb, x, y) + 2.0f * m;
        float fc     = __ldg(fb + x * NYc + y);
        r[j] = fmaxf(fmaf(-gradAf + 0.5f * gvv, dtb, fc), 0.0f);
    }
    *(float4*)(ob + x * NYc + y0) = make_float4(r[0], r[1], r[2], r[3]);
}

// ======================= fast path (software-pipelined) =======================
// Whole update collapses to:  out(x) = max(P'(x+1) + M'(x-1) + C'(x), 0)
//   P' = 0.5*dt*(b0 + g2 - a0)
//   M' = 0.5*dt*(b0 - g2 + a0)
//   C' = dt*(0.5*hB1 - b0 - hA1) + f
// a0=A0*f, b0=B0*f, g2=d/dy(B2*f), hA1=d/dy(A1*f), hB1=d2/dy2(B1*f).
// Loop pipelines: raw loads of row x+2 issued while combining row x,
// consumed (ALU reduction) only in the NEXT iteration.

struct Raw {
    float4 fv, a0, a1, b0, b1, b2;
    float fm1, fp4, a1m1, a1p4, b1m1, b1p4, b2m1, b2p4;
};

__device__ __forceinline__ void load_raw(
    Raw& R, int r, int y0, bool le, bool re,
    const float* __restrict__ fb,
    const float* __restrict__ A0, const float* __restrict__ A1,
    const float* __restrict__ B0, const float* __restrict__ B1,
    const float* __restrict__ B2)
{
    const int base = r * NYc + y0;
    R.fv = *(const float4*)(fb + base);
    R.a0 = *(const float4*)(A0 + base);
    R.a1 = *(const float4*)(A1 + base);
    R.b0 = *(const float4*)(B0 + base);
    R.b1 = *(const float4*)(B1 + base);
    R.b2 = *(const float4*)(B2 + base);
    R.fm1  = le ? 0.0f : __ldg(fb + base - 1);
    R.a1m1 = le ? 0.0f : __ldg(A1 + base - 1);
    R.b1m1 = le ? 0.0f : __ldg(B1 + base - 1);
    R.b2m1 = le ? 0.0f : __ldg(B2 + base - 1);
    R.fp4  = re ? 0.0f : __ldg(fb + base + 4);
    R.a1p4 = re ? 0.0f : __ldg(A1 + base + 4);
    R.b1p4 = re ? 0.0f : __ldg(B1 + base + 4);
    R.b2p4 = re ? 0.0f : __ldg(B2 + base + 4);
}

// pure-ALU reduction of a Raw row into P', M', C' (dt folded in)
__device__ __forceinline__ void reduce_row(
    const Raw& R, bool le, bool re, float dtb, float hd,
    float* __restrict__ P, float* __restrict__ M, float* __restrict__ C)
{
    float fv[6] = {R.fm1, R.fv.x, R.fv.y, R.fv.z, R.fv.w, R.fp4};

    float a0p[4] = {R.a0.x * fv[1], R.a0.y * fv[2], R.a0.z * fv[3], R.a0.w * fv[4]};
    float b0p[4] = {R.b0.x * fv[1], R.b0.y * fv[2], R.b0.z * fv[3], R.b0.w * fv[4]};

    float p[6], hA1[4], hB1[4], g2[4];

    // A1: d/dy
    p[0] = R.a1m1 * fv[0];
    p[1] = R.a1.x * fv[1]; p[2] = R.a1.y * fv[2];
    p[3] = R.a1.z * fv[3]; p[4] = R.a1.w * fv[4];
    p[5] = R.a1p4 * fv[5];
#pragma unroll
    for (int j = 0; j < 4; j++) hA1[j] = 0.5f * (p[j + 2] - p[j]);
    if (le) hA1[0] = 0.5f * (-3.0f * p[1] + 4.0f * p[2] - p[3]);
    if (re) hA1[3] = 0.5f * ( 3.0f * p[4] - 4.0f * p[3] + p[2]);

    // B1: d2/dy2
    p[0] = R.b1m1 * fv[0];
    p[1] = R.b1.x * fv[1]; p[2] = R.b1.y * fv[2];
    p[3] = R.b1.z * fv[3]; p[4] = R.b1.w * fv[4];
    p[5] = R.b1p4 * fv[5];
#pragma unroll
    for (int j = 0; j < 4; j++) hB1[j] = p[j + 2] - 2.0f * p[j + 1] + p[j];
    if (le) hB1[0] = 2.0f * p[1] - 5.0f * p[2] + 4.0f * p[3] - p[4];
    if (re) hB1[3] = 2.0f * p[4] - 5.0f * p[3] + 4.0f * p[2] - p[1];

    // B2: d/dy
    p[0] = R.b2m1 * fv[0];
    p[1] = R.b2.x * fv[1]; p[2] = R.b2.y * fv[2];
    p[3] = R.b2.z * fv[3]; p[4] = R.b2.w * fv[4];
    p[5] = R.b2p4 * fv[5];
#pragma unroll
    for (int j = 0; j < 4; j++) g2[j] = 0.5f * (p[j + 2] - p[j]);
    if (le) g2[0] = 0.5f * (-3.0f * p[1] + 4.0f * p[2] - p[3]);
    if (re) g2[3] = 0.5f * ( 3.0f * p[4] - 4.0f * p[3] + p[2]);

#pragma unroll
    for (int j = 0; j < 4; j++) {
        P[j] = hd * (b0p[j] + g2[j] - a0p[j]);
        M[j] = hd * (b0p[j] - g2[j] + a0p[j]);
        C[j] = fmaf(dtb, 0.5f * hB1[j] - b0p[j] - hA1[j], fv[j + 1]);
    }
}

__global__ void __launch_bounds__(256, 3)
fp_fast(const float* __restrict__ f, const float* __restrict__ A,
        const float* __restrict__ Bg, const float* __restrict__ dt,
        float* __restrict__ out)
{
    const int y0    = threadIdx.x * 4;
    const int chunk = blockIdx.x;
    const int b     = blockIdx.y;
    const bool le = (y0 == 0);
    const bool re = (y0 == NYc - 4);

    const float* fb = f + (size_t)b * PLANE;
    const float* A0 = A;
    const float* A1 = A + PLANE;
    const float* B0 = Bg;
    const float* B1 = Bg + PLANE;
    const float* B2 = Bg + 2 * PLANE;
    const float dtb = __ldg(dt + b);
    const float hd  = 0.5f * dtb;
    float* ob = out + (size_t)b * PLANE;

    const int xs = chunk * ROWS_PER_BLOCK;
    const int xe = xs + ROWS_PER_BLOCK;

    Raw R;
    float Pn[4], Mn[4], Cn[4];
    float Mm[4], Mc[4], Cc[4];

    int x0;
    if (xs == 0) {
        slow_row(0, y0, fb, A0, A1, B0, B1, B2, dtb, ob);
        load_raw(R, 0, y0, le, re, fb, A0, A1, B0, B1, B2);
        reduce_row(R, le, re, dtb, hd, Pn, Mm, Cn);
        load_raw(R, 1, y0, le, re, fb, A0, A1, B0, B1, B2);
        reduce_row(R, le, re, dtb, hd, Pn, Mc, Cc);
        x0 = 1;
    } else {
        load_raw(R, xs - 1, y0, le, re, fb, A0, A1, B0, B1, B2);
        reduce_row(R, le, re, dtb, hd, Pn, Mm, Cn);
        load_raw(R, xs, y0, le, re, fb, A0, A1, B0, B1, B2);
        reduce_row(R, le, re, dtb, hd, Pn, Mc, Cc);
        x0 = xs;
    }
    const int xlast = (xe == NXc) ? NXc - 1 : xe;

    // prefetch row x0+1
    load_raw(R, x0 + 1, y0, le, re, fb, A0, A1, B0, B1, B2);

#pragma unroll 2
    for (int x = x0; x < xlast; x++) {
        // reduce row x+1 (its raw data was loaded one iteration ago)
        reduce_row(R, le, re, dtb, hd, Pn, Mn, Cn);

        // prefetch row x+2 (clamped; tail load is harmless)
        int nr = x + 2;
        if (nr > NXc - 1) nr = NXc - 1;
        load_raw(R, nr, y0, le, re, fb, A0, A1, B0, B1, B2);

        // output row x
        float r[4];
#pragma unroll
        for (int j = 0; j < 4; j++)
            r[j] = fmaxf(Pn[j] + Mm[j] + Cc[j], 0.0f);
        *(float4*)(ob + x * NYc + y0) = make_float4(r[0], r[1], r[2], r[3]);

#pragma unroll
        for (int j = 0; j < 4; j++) {
            Mm[j] = Mc[j]; Mc[j] = Mn[j]; Cc[j] = Cn[j];
        }
    }

    if (xe == NXc) {
        slow_row(NXc - 1, y0, fb, A0, A1, B0, B1, B2, dtb, ob);
    }
}

extern "C" void kernel_launch(void* const* d_in, const int* in_sizes, int n_in,
                              void* d_out, int out_size) {
    const float* f  = (const float*)d_in[0];   // [16,1024,1024]
    const float* A  = (const float*)d_in[1];   // [2,1024,1024]
    const float* Bg = (const float*)d_in[2];   // [3,1024,1024]
    const float* dt = (const float*)d_in[3];   // [16]
    float* out = (float*)d_out;

    dim3 block(256, 1, 1);
    dim3 grid(XCHUNKS, NB, 1);
    fp_fast<<<grid, block>>>(f, A, Bg, dt, out);
}